// round 2
// baseline (speedup 1.0000x reference)
#include <cuda_runtime.h>
#include <cstdint>

#define NB 8
#define RES 160
#define GCELLS (NB * RES * RES * RES)   // 32,768,000
#define EMA 0.95f
#define THRE 0.01f

// Scratch: per-cell max of (float bits of val) + 1. 0 == untouched sentinel.
// Zero-initialized at module load; sweep kernel resets touched entries so the
// state is identical at the start of every graph replay.
__device__ unsigned int g_scratch[GCELLS];

__global__ void scatter_max_kernel(const float* __restrict__ pts,
                                   const int* __restrict__ bidx,
                                   const float* __restrict__ val,
                                   int n) {
    int i = blockIdx.x * blockDim.x + threadIdx.x;
    if (i >= n) return;

    float px = __ldg(&pts[3 * i + 0]);
    float py = __ldg(&pts[3 * i + 1]);
    float pz = __ldg(&pts[3 * i + 2]);

    // exactly matches ((p/2 + 0.5) * res).astype(int32) then clip
    int gx = (int)((px * 0.5f + 0.5f) * (float)RES);
    int gy = (int)((py * 0.5f + 0.5f) * (float)RES);
    int gz = (int)((pz * 0.5f + 0.5f) * (float)RES);
    gx = min(max(gx, 0), RES - 1);
    gy = min(max(gy, 0), RES - 1);
    gz = min(max(gz, 0), RES - 1);

    int b = __ldg(&bidx[i]);
    int lin = ((b * RES + gx) * RES + gy) * RES + gz;

    // vals are nonnegative floats: bit pattern order == value order.
    // +1 reserves 0 as the untouched sentinel (no overflow: val <= ~0.05).
    unsigned int v = __float_as_uint(__ldg(&val[i])) + 1u;
    atomicMax(&g_scratch[lin], v);
}

__global__ void sweep_kernel(const float4* __restrict__ in,
                             float4* __restrict__ out_grid,
                             float4* __restrict__ out_occ,
                             int nvec, int write_occ) {
    int i = blockIdx.x * blockDim.x + threadIdx.x;
    if (i >= nvec) return;

    float4 g = __ldg(&in[i]);
    uint4 s = reinterpret_cast<const uint4*>(g_scratch)[i];

    float4 o;
    o.x = s.x ? fmaxf(g.x * EMA, __uint_as_float(s.x - 1u)) : g.x;
    o.y = s.y ? fmaxf(g.y * EMA, __uint_as_float(s.y - 1u)) : g.y;
    o.z = s.z ? fmaxf(g.z * EMA, __uint_as_float(s.z - 1u)) : g.z;
    o.w = s.w ? fmaxf(g.w * EMA, __uint_as_float(s.w - 1u)) : g.w;

    out_grid[i] = o;

    if (write_occ) {
        float4 q;
        q.x = (o.x > THRE) ? 1.0f : 0.0f;
        q.y = (o.y > THRE) ? 1.0f : 0.0f;
        q.z = (o.z > THRE) ? 1.0f : 0.0f;
        q.w = (o.w > THRE) ? 1.0f : 0.0f;
        out_occ[i] = q;
    }

    // Reset only touched vectors (saves ~60% of the reset writes).
    if (s.x | s.y | s.z | s.w) {
        reinterpret_cast<uint4*>(g_scratch)[i] = make_uint4(0u, 0u, 0u, 0u);
    }
}

extern "C" void kernel_launch(void* const* d_in, const int* in_sizes, int n_in,
                              void* d_out, int out_size) {
    const float* grid_in = (const float*)d_in[0];   // occ_val_grid [8,160,160,160] f32
    const float* pts     = (const float*)d_in[1];   // [N,3] f32
    const int*   bidx    = (const int*)d_in[2];     // [N] i32
    const float* val     = (const float*)d_in[3];   // [N] f32

    int n = in_sizes[3];                 // N points
    float* out = (float*)d_out;

    int write_occ = (out_size >= 2 * GCELLS) ? 1 : 0;
    float4* out_grid = (float4*)out;
    float4* out_occ  = (float4*)(out + GCELLS);

    {
        int threads = 256;
        int blocks = (n + threads - 1) / threads;
        scatter_max_kernel<<<blocks, threads>>>(pts, bidx, val, n);
    }
    {
        int nvec = GCELLS / 4;           // 8,192,000
        int threads = 256;
        int blocks = (nvec + threads - 1) / threads;
        sweep_kernel<<<blocks, threads>>>((const float4*)grid_in, out_grid,
                                          out_occ, nvec, write_occ);
    }
}

// round 4
// speedup vs baseline: 1.1012x; 1.1012x over previous
#include <cuda_runtime.h>
#include <cstdint>

#define NB 8
#define RES 160
#define GCELLS (NB * RES * RES * RES)   // 32,768,000
#define EMA 0.95f
#define THRE 0.01f

// Scratch: per-cell max of (float bits of val) + 1. 0 == untouched sentinel.
// Zero-initialized at module load; sweep kernel resets touched entries so the
// state is identical at the start of every graph replay.
__device__ unsigned int g_scratch[GCELLS];

__device__ __forceinline__ int cell_coord(float p) {
    int g = (int)((p * 0.5f + 0.5f) * (float)RES);
    return min(max(g, 0), RES - 1);
}

// 4 points per thread, fully vectorized + streaming (evict-first) loads so the
// point streams don't evict the scratch array from L2.
__global__ void scatter_max4_kernel(const float4* __restrict__ pts4,
                                    const int4* __restrict__ bidx4,
                                    const float4* __restrict__ val4,
                                    int n4) {
    int i = blockIdx.x * blockDim.x + threadIdx.x;
    if (i >= n4) return;

    float4 p0 = __ldcs(&pts4[3 * i + 0]);
    float4 p1 = __ldcs(&pts4[3 * i + 1]);
    float4 p2 = __ldcs(&pts4[3 * i + 2]);
    int4   b  = __ldcs(&bidx4[i]);
    float4 v  = __ldcs(&val4[i]);

    // point layout within the 12 floats:
    // pt0=(p0.x,p0.y,p0.z) pt1=(p0.w,p1.x,p1.y) pt2=(p1.z,p1.w,p2.x) pt3=(p2.y,p2.z,p2.w)
    int l0 = ((b.x * RES + cell_coord(p0.x)) * RES + cell_coord(p0.y)) * RES + cell_coord(p0.z);
    int l1 = ((b.y * RES + cell_coord(p0.w)) * RES + cell_coord(p1.x)) * RES + cell_coord(p1.y);
    int l2 = ((b.z * RES + cell_coord(p1.z)) * RES + cell_coord(p1.w)) * RES + cell_coord(p2.x);
    int l3 = ((b.w * RES + cell_coord(p2.y)) * RES + cell_coord(p2.z)) * RES + cell_coord(p2.w);

    // nonnegative floats: bit order == value order; +1 reserves 0 as sentinel.
    atomicMax(&g_scratch[l0], __float_as_uint(v.x) + 1u);
    atomicMax(&g_scratch[l1], __float_as_uint(v.y) + 1u);
    atomicMax(&g_scratch[l2], __float_as_uint(v.z) + 1u);
    atomicMax(&g_scratch[l3], __float_as_uint(v.w) + 1u);
}

// scalar tail (only launched if n % 4 != 0; n = 4194304 here so normally unused)
__global__ void scatter_max_tail_kernel(const float* __restrict__ pts,
                                        const int* __restrict__ bidx,
                                        const float* __restrict__ val,
                                        int start, int n) {
    int i = start + blockIdx.x * blockDim.x + threadIdx.x;
    if (i >= n) return;
    int gx = cell_coord(pts[3 * i + 0]);
    int gy = cell_coord(pts[3 * i + 1]);
    int gz = cell_coord(pts[3 * i + 2]);
    int lin = ((bidx[i] * RES + gx) * RES + gy) * RES + gz;
    atomicMax(&g_scratch[lin], __float_as_uint(val[i]) + 1u);
}

__global__ void sweep_kernel(const float4* __restrict__ in,
                             float4* __restrict__ out_grid,
                             float4* __restrict__ out_occ,
                             int nvec, int write_occ) {
    int i = blockIdx.x * blockDim.x + threadIdx.x;
    if (i >= nvec) return;

    float4 g = __ldcs(&in[i]);
    uint4 s = reinterpret_cast<const uint4*>(g_scratch)[i];

    float4 o;
    o.x = s.x ? fmaxf(g.x * EMA, __uint_as_float(s.x - 1u)) : g.x;
    o.y = s.y ? fmaxf(g.y * EMA, __uint_as_float(s.y - 1u)) : g.y;
    o.z = s.z ? fmaxf(g.z * EMA, __uint_as_float(s.z - 1u)) : g.z;
    o.w = s.w ? fmaxf(g.w * EMA, __uint_as_float(s.w - 1u)) : g.w;

    __stcs(&out_grid[i], o);

    if (write_occ) {
        float4 q;
        q.x = (o.x > THRE) ? 1.0f : 0.0f;
        q.y = (o.y > THRE) ? 1.0f : 0.0f;
        q.z = (o.z > THRE) ? 1.0f : 0.0f;
        q.w = (o.w > THRE) ? 1.0f : 0.0f;
        __stcs(&out_occ[i], q);
    }

    // Reset only touched vectors so the next replay starts from zeros.
    if (s.x | s.y | s.z | s.w) {
        reinterpret_cast<uint4*>(g_scratch)[i] = make_uint4(0u, 0u, 0u, 0u);
    }
}

extern "C" void kernel_launch(void* const* d_in, const int* in_sizes, int n_in,
                              void* d_out, int out_size) {
    const float* grid_in = (const float*)d_in[0];   // occ_val_grid [8,160,160,160] f32
    const float* pts     = (const float*)d_in[1];   // [N,3] f32
    const int*   bidx    = (const int*)d_in[2];     // [N] i32
    const float* val     = (const float*)d_in[3];   // [N] f32

    int n = in_sizes[3];                 // N points
    float* out = (float*)d_out;

    int write_occ = (out_size >= 2 * GCELLS) ? 1 : 0;
    float4* out_grid = (float4*)out;
    float4* out_occ  = (float4*)(out + GCELLS);

    int n4 = n / 4;
    int rem = n - n4 * 4;
    if (n4 > 0) {
        int threads = 256;
        int blocks = (n4 + threads - 1) / threads;
        scatter_max4_kernel<<<blocks, threads>>>((const float4*)pts,
                                                 (const int4*)bidx,
                                                 (const float4*)val, n4);
    }
    if (rem > 0) {
        scatter_max_tail_kernel<<<1, 128>>>(pts, bidx, val, n4 * 4, n);
    }
    {
        int nvec = GCELLS / 4;           // 8,192,000
        int threads = 256;
        int blocks = (nvec + threads - 1) / threads;
        sweep_kernel<<<blocks, threads>>>((const float4*)grid_in, out_grid,
                                          out_occ, nvec, write_occ);
    }
}